// round 2
// baseline (speedup 1.0000x reference)
#include <cuda_runtime.h>
#include <math.h>

// Problem constants
#define BB 4
#define NN 2048
#define CC 768
#define HH 12
#define HDIM 64
#define SCALE 0.125f   // 64^-0.5

// Scratch (no cudaMalloc allowed -> __device__ globals)
__device__ float g_q[BB * HH * NN * HDIM];     // [B,H,N,HD], pre-scaled
__device__ float g_k[BB * HH * NN * HDIM];
__device__ float g_v[BB * HH * NN * HDIM];
__device__ float g_att[BB * NN * CC];          // attention output, [B,N,C]

// ---------------------------------------------------------------------------
// SGEMM 128x128x8, 256 threads, 8x8 microtile (strided-16 mapping).
// Two variants differing only in epilogue.
// ---------------------------------------------------------------------------

__global__ __launch_bounds__(256) void qkv_gemm(
    const float* __restrict__ X,      // [8192, 768]
    const float* __restrict__ W,      // [768, 2304]
    const float* __restrict__ bias)   // [2304]
{
    __shared__ float As[8][128];
    __shared__ float Bs[8][128];

    const int tid = threadIdx.x;
    const int m0 = blockIdx.y * 128;
    const int n0 = blockIdx.x * 128;

    const int aRow = tid >> 1;           // 0..127
    const int aCol = (tid & 1) * 4;      // 0 or 4
    const int bRow = tid >> 5;           // 0..7
    const int bCol = (tid & 31) * 4;     // 0..124

    const int tr = tid >> 4;             // 0..15
    const int tc = tid & 15;             // 0..15

    float acc[8][8];
#pragma unroll
    for (int i = 0; i < 8; i++)
#pragma unroll
        for (int j = 0; j < 8; j++) acc[i][j] = 0.f;

    for (int k0 = 0; k0 < CC; k0 += 8) {
        float4 av = *(const float4*)&X[(m0 + aRow) * CC + k0 + aCol];
        As[aCol + 0][aRow] = av.x;
        As[aCol + 1][aRow] = av.y;
        As[aCol + 2][aRow] = av.z;
        As[aCol + 3][aRow] = av.w;
        float4 bv = *(const float4*)&W[(k0 + bRow) * (3 * CC) + n0 + bCol];
        *(float4*)&Bs[bRow][bCol] = bv;
        __syncthreads();

#pragma unroll
        for (int kk = 0; kk < 8; kk++) {
            float a[8], b[8];
#pragma unroll
            for (int i = 0; i < 8; i++) a[i] = As[kk][tr + 16 * i];
#pragma unroll
            for (int j = 0; j < 8; j++) b[j] = Bs[kk][tc + 16 * j];
#pragma unroll
            for (int i = 0; i < 8; i++)
#pragma unroll
                for (int j = 0; j < 8; j++) acc[i][j] += a[i] * b[j];
        }
        __syncthreads();
    }

    // Epilogue: scatter to q/k/v in [B,H,N,HD]; q pre-scaled.
#pragma unroll
    for (int i = 0; i < 8; i++) {
        int row = m0 + tr + 16 * i;       // 0..8191 = b*N + n
        int b_ = row >> 11;               // row / 2048
        int n = row & (NN - 1);
#pragma unroll
        for (int j = 0; j < 8; j++) {
            int col = n0 + tc + 16 * j;   // 0..2303
            float v = acc[i][j] + bias[col];
            int three = col / CC;
            int rem = col - three * CC;
            int h = rem >> 6;
            int hd = rem & 63;
            int idx = ((b_ * HH + h) * NN + n) * HDIM + hd;
            if (three == 0)       g_q[idx] = v * SCALE;
            else if (three == 1)  g_k[idx] = v;
            else                  g_v[idx] = v;
        }
    }
}

__global__ __launch_bounds__(256) void proj_gemm(
    const float* __restrict__ W,      // [768, 768]
    const float* __restrict__ bias,   // [768]
    float* __restrict__ out)          // [8192, 768]
{
    __shared__ float As[8][128];
    __shared__ float Bs[8][128];

    const float* __restrict__ A = g_att;   // device symbol, referenced device-side

    const int tid = threadIdx.x;
    const int m0 = blockIdx.y * 128;
    const int n0 = blockIdx.x * 128;

    const int aRow = tid >> 1;
    const int aCol = (tid & 1) * 4;
    const int bRow = tid >> 5;
    const int bCol = (tid & 31) * 4;

    const int tr = tid >> 4;
    const int tc = tid & 15;

    float acc[8][8];
#pragma unroll
    for (int i = 0; i < 8; i++)
#pragma unroll
        for (int j = 0; j < 8; j++) acc[i][j] = 0.f;

    for (int k0 = 0; k0 < CC; k0 += 8) {
        float4 av = *(const float4*)&A[(m0 + aRow) * CC + k0 + aCol];
        As[aCol + 0][aRow] = av.x;
        As[aCol + 1][aRow] = av.y;
        As[aCol + 2][aRow] = av.z;
        As[aCol + 3][aRow] = av.w;
        float4 bv = *(const float4*)&W[(k0 + bRow) * CC + n0 + bCol];
        *(float4*)&Bs[bRow][bCol] = bv;
        __syncthreads();

#pragma unroll
        for (int kk = 0; kk < 8; kk++) {
            float a[8], b[8];
#pragma unroll
            for (int i = 0; i < 8; i++) a[i] = As[kk][tr + 16 * i];
#pragma unroll
            for (int j = 0; j < 8; j++) b[j] = Bs[kk][tc + 16 * j];
#pragma unroll
            for (int i = 0; i < 8; i++)
#pragma unroll
                for (int j = 0; j < 8; j++) acc[i][j] += a[i] * b[j];
        }
        __syncthreads();
    }

#pragma unroll
    for (int i = 0; i < 8; i++) {
        int row = m0 + tr + 16 * i;
#pragma unroll
        for (int j = 0; j < 8; j++) {
            int col = n0 + tc + 16 * j;
            out[row * CC + col] = acc[i][j] + bias[col];
        }
    }
}

// ---------------------------------------------------------------------------
// Flash attention (fp32). One CTA per (b*H+h, 128-query block).
// 256 threads: ty = tid/8 (row group of 4 rows), tx = tid%8.
// S cols mapped c = cc*8+tx, O cols d = dd*8+tx (conflict-free, pitch 65).
// ---------------------------------------------------------------------------

#define FA_PITCH 65

__global__ __launch_bounds__(256) void flash_attn() {
    extern __shared__ float sm[];
    float* Qs = sm;                          // 128 * 65
    float* Ks = Qs + 128 * FA_PITCH;         // 64 * 65
    float* Vs = Ks + 64 * FA_PITCH;          // 64 * 65
    float* Ps = Vs + 64 * FA_PITCH;          // 128 * 65

    const int tid = threadIdx.x;
    const int bh = blockIdx.y;               // 0..47
    const int n0 = blockIdx.x * 128;

    const float* __restrict__ Qg = g_q + bh * (NN * HDIM);
    const float* __restrict__ Kg = g_k + bh * (NN * HDIM);
    const float* __restrict__ Vg = g_v + bh * (NN * HDIM);

    const int ty = tid >> 3;                 // 0..31
    const int tx = tid & 7;                  // 0..7

    // Load Q block [128, 64]
    for (int i = tid; i < 128 * 16; i += 256) {
        int r = i >> 4;
        int c = (i & 15) * 4;
        float4 v = *(const float4*)&Qg[(n0 + r) * HDIM + c];
        Qs[r * FA_PITCH + c + 0] = v.x;
        Qs[r * FA_PITCH + c + 1] = v.y;
        Qs[r * FA_PITCH + c + 2] = v.z;
        Qs[r * FA_PITCH + c + 3] = v.w;
    }

    float m[4], l[4], o[4][8];
#pragma unroll
    for (int rr = 0; rr < 4; rr++) {
        m[rr] = -1e30f;
        l[rr] = 0.f;
#pragma unroll
        for (int dd = 0; dd < 8; dd++) o[rr][dd] = 0.f;
    }

    for (int j0 = 0; j0 < NN; j0 += 64) {
        __syncthreads();  // prev iter consumers of Ks/Vs/Ps done
        // Load K/V tiles [64, 64]
        for (int i = tid; i < 64 * 16; i += 256) {
            int r = i >> 4;
            int c = (i & 15) * 4;
            float4 kv = *(const float4*)&Kg[(j0 + r) * HDIM + c];
            Ks[r * FA_PITCH + c + 0] = kv.x;
            Ks[r * FA_PITCH + c + 1] = kv.y;
            Ks[r * FA_PITCH + c + 2] = kv.z;
            Ks[r * FA_PITCH + c + 3] = kv.w;
            float4 vv = *(const float4*)&Vg[(j0 + r) * HDIM + c];
            Vs[r * FA_PITCH + c + 0] = vv.x;
            Vs[r * FA_PITCH + c + 1] = vv.y;
            Vs[r * FA_PITCH + c + 2] = vv.z;
            Vs[r * FA_PITCH + c + 3] = vv.w;
        }
        __syncthreads();

        // S = Q @ K^T tile: s[4][8], rows ty*4+rr, cols cc*8+tx
        float s[4][8];
#pragma unroll
        for (int rr = 0; rr < 4; rr++)
#pragma unroll
            for (int cc = 0; cc < 8; cc++) s[rr][cc] = 0.f;

        for (int k = 0; k < HDIM; k++) {
            float a[4], b[8];
#pragma unroll
            for (int rr = 0; rr < 4; rr++) a[rr] = Qs[(ty * 4 + rr) * FA_PITCH + k];
#pragma unroll
            for (int cc = 0; cc < 8; cc++) b[cc] = Ks[(cc * 8 + tx) * FA_PITCH + k];
#pragma unroll
            for (int rr = 0; rr < 4; rr++)
#pragma unroll
                for (int cc = 0; cc < 8; cc++) s[rr][cc] += a[rr] * b[cc];
        }

        // Online softmax (row stats across the 8 tx lanes sharing a row)
#pragma unroll
        for (int rr = 0; rr < 4; rr++) {
            float tmax = s[rr][0];
#pragma unroll
            for (int cc = 1; cc < 8; cc++) tmax = fmaxf(tmax, s[rr][cc]);
            tmax = fmaxf(tmax, __shfl_xor_sync(0xffffffffu, tmax, 1));
            tmax = fmaxf(tmax, __shfl_xor_sync(0xffffffffu, tmax, 2));
            tmax = fmaxf(tmax, __shfl_xor_sync(0xffffffffu, tmax, 4));

            float nm = fmaxf(m[rr], tmax);
            float corr = __expf(m[rr] - nm);
            float sum = 0.f;
#pragma unroll
            for (int cc = 0; cc < 8; cc++) {
                float p = __expf(s[rr][cc] - nm);
                s[rr][cc] = p;
                sum += p;
            }
            sum += __shfl_xor_sync(0xffffffffu, sum, 1);
            sum += __shfl_xor_sync(0xffffffffu, sum, 2);
            sum += __shfl_xor_sync(0xffffffffu, sum, 4);

            l[rr] = l[rr] * corr + sum;
            m[rr] = nm;
#pragma unroll
            for (int dd = 0; dd < 8; dd++) o[rr][dd] *= corr;
        }

        // Stage P
#pragma unroll
        for (int rr = 0; rr < 4; rr++)
#pragma unroll
            for (int cc = 0; cc < 8; cc++)
                Ps[(ty * 4 + rr) * FA_PITCH + cc * 8 + tx] = s[rr][cc];
        __syncthreads();

        // O += P @ V
        for (int j = 0; j < 64; j++) {
            float a[4], b[8];
#pragma unroll
            for (int rr = 0; rr < 4; rr++) a[rr] = Ps[(ty * 4 + rr) * FA_PITCH + j];
#pragma unroll
            for (int dd = 0; dd < 8; dd++) b[dd] = Vs[j * FA_PITCH + dd * 8 + tx];
#pragma unroll
            for (int rr = 0; rr < 4; rr++)
#pragma unroll
                for (int dd = 0; dd < 8; dd++) o[rr][dd] += a[rr] * b[dd];
        }
    }

    // Write O / l to g_att in [B, N, C] layout
    const int b_ = bh / HH;
    const int h = bh % HH;
#pragma unroll
    for (int rr = 0; rr < 4; rr++) {
        float inv = 1.f / l[rr];
        int n = n0 + ty * 4 + rr;
#pragma unroll
        for (int dd = 0; dd < 8; dd++) {
            int d = dd * 8 + tx;
            g_att[(b_ * NN + n) * CC + h * HDIM + d] = o[rr][dd] * inv;
        }
    }
}

// ---------------------------------------------------------------------------

extern "C" void kernel_launch(void* const* d_in, const int* in_sizes, int n_in,
                              void* d_out, int out_size) {
    const float* x      = (const float*)d_in[0];  // [4,2048,768]
    const float* w_qkv  = (const float*)d_in[1];  // [768,2304]
    const float* b_qkv  = (const float*)d_in[2];  // [2304]
    const float* w_proj = (const float*)d_in[3];  // [768,768]
    const float* b_proj = (const float*)d_in[4];  // [768]
    float* out = (float*)d_out;

    // 1) QKV projection
    {
        dim3 grid((3 * CC) / 128, (BB * NN) / 128);  // 18 x 64
        qkv_gemm<<<grid, 256>>>(x, w_qkv, b_qkv);
    }

    // 2) Flash attention
    {
        int smem = (128 + 64 + 64 + 128) * FA_PITCH * sizeof(float);  // 99840 B
        cudaFuncSetAttribute(flash_attn, cudaFuncAttributeMaxDynamicSharedMemorySize, smem);
        dim3 grid(NN / 128, BB * HH);  // 16 x 48
        flash_attn<<<grid, 256, smem>>>();
    }

    // 3) Output projection
    {
        dim3 grid(CC / 128, (BB * NN) / 128);  // 6 x 64
        proj_gemm<<<grid, 256>>>(w_proj, b_proj, out);
    }
}

// round 3
// speedup vs baseline: 3.0976x; 3.0976x over previous
#include <cuda_runtime.h>
#include <math.h>
#include <stdint.h>

// Problem constants
#define BB 4
#define NN 2048
#define CC 768
#define HH 12
#define HDIM 64
#define SCALE 0.125f   // 64^-0.5

// Scratch (no cudaMalloc allowed -> __device__ globals)
__device__ float g_q[BB * HH * NN * HDIM];     // [B,H,N,HD], pre-scaled
__device__ float g_k[BB * HH * NN * HDIM];
__device__ float g_v[BB * HH * NN * HDIM];
__device__ float g_att[BB * NN * CC];          // attention output, [B,N,C]

__device__ __forceinline__ uint32_t f2tf32(float x) {
    uint32_t r;
    asm("cvt.rna.tf32.f32 %0, %1;" : "=r"(r) : "f"(x));
    return r;
}

__device__ __forceinline__ void mma_tf32(float c[4],
                                         uint32_t a0, uint32_t a1, uint32_t a2, uint32_t a3,
                                         uint32_t b0, uint32_t b1) {
    asm volatile(
        "mma.sync.aligned.m16n8k8.row.col.f32.tf32.tf32.f32 "
        "{%0,%1,%2,%3}, {%4,%5,%6,%7}, {%8,%9}, {%0,%1,%2,%3};"
        : "+f"(c[0]), "+f"(c[1]), "+f"(c[2]), "+f"(c[3])
        : "r"(a0), "r"(a1), "r"(a2), "r"(a3), "r"(b0), "r"(b1));
}

// ---------------------------------------------------------------------------
// tf32 MMA GEMM, CTA tile 128x128, Kstep=16, 8 warps (64x32 each).
// As: [k][m] stride 136 (conflict-free frag loads), Bs: [k][n] stride 136.
// ---------------------------------------------------------------------------

#define GP 136

template <int LDW, bool IS_QKV>
__device__ __forceinline__ void gemm_body(
    const float* __restrict__ A,   // [8192, 768] row-major
    const float* __restrict__ W,   // [768, LDW]  row-major
    const float* __restrict__ bias,
    float* __restrict__ out)       // used when !IS_QKV
{
    __shared__ uint32_t As[16][GP];
    __shared__ uint32_t Bs[16][GP];

    const int tid = threadIdx.x;
    const int warp = tid >> 5;
    const int lane = tid & 31;
    const int g = lane >> 2;       // 0..7
    const int tg = lane & 3;       // 0..3

    const int m0 = blockIdx.y * 128;
    const int n0 = blockIdx.x * 128;
    const int warp_m = (warp >> 2) * 64;
    const int warp_n = (warp & 3) * 32;

    float acc[4][4][4];
#pragma unroll
    for (int mt = 0; mt < 4; mt++)
#pragma unroll
        for (int nt = 0; nt < 4; nt++)
#pragma unroll
            for (int r = 0; r < 4; r++) acc[mt][nt][r] = 0.f;

    for (int k0 = 0; k0 < CC; k0 += 16) {
        float4 av[2], bv[2];
#pragma unroll
        for (int i = 0; i < 2; i++) {
            int f = tid + i * 256;           // 0..511
            int arow = f >> 2, ak = f & 3;
            av[i] = *(const float4*)&A[(m0 + arow) * CC + k0 + ak * 4];
            int bk = f >> 5, bn = f & 31;
            bv[i] = *(const float4*)&W[(k0 + bk) * LDW + n0 + bn * 4];
        }
        __syncthreads();
#pragma unroll
        for (int i = 0; i < 2; i++) {
            int f = tid + i * 256;
            int arow = f >> 2, ak = f & 3;
            As[ak * 4 + 0][arow] = f2tf32(av[i].x);
            As[ak * 4 + 1][arow] = f2tf32(av[i].y);
            As[ak * 4 + 2][arow] = f2tf32(av[i].z);
            As[ak * 4 + 3][arow] = f2tf32(av[i].w);
            int bk = f >> 5, bn = f & 31;
            uint4 bu;
            bu.x = f2tf32(bv[i].x); bu.y = f2tf32(bv[i].y);
            bu.z = f2tf32(bv[i].z); bu.w = f2tf32(bv[i].w);
            *(uint4*)&Bs[bk][bn * 4] = bu;
        }
        __syncthreads();

#pragma unroll
        for (int kk = 0; kk < 16; kk += 8) {
            uint32_t a[4][4], b[4][2];
#pragma unroll
            for (int mt = 0; mt < 4; mt++) {
                int mr = warp_m + mt * 16 + g;
                a[mt][0] = As[kk + tg][mr];
                a[mt][1] = As[kk + tg][mr + 8];
                a[mt][2] = As[kk + tg + 4][mr];
                a[mt][3] = As[kk + tg + 4][mr + 8];
            }
#pragma unroll
            for (int nt = 0; nt < 4; nt++) {
                int nc = warp_n + nt * 8 + g;
                b[nt][0] = Bs[kk + tg][nc];
                b[nt][1] = Bs[kk + tg + 4][nc];
            }
#pragma unroll
            for (int mt = 0; mt < 4; mt++)
#pragma unroll
                for (int nt = 0; nt < 4; nt++)
                    mma_tf32(acc[mt][nt], a[mt][0], a[mt][1], a[mt][2], a[mt][3],
                             b[nt][0], b[nt][1]);
        }
        __syncthreads();
    }

    // Epilogue
#pragma unroll
    for (int mt = 0; mt < 4; mt++) {
#pragma unroll
        for (int nt = 0; nt < 4; nt++) {
#pragma unroll
            for (int half = 0; half < 2; half++) {
                int row = m0 + warp_m + mt * 16 + g + half * 8;
#pragma unroll
                for (int cb = 0; cb < 2; cb++) {
                    int col = n0 + warp_n + nt * 8 + 2 * tg + cb;
                    float v = acc[mt][nt][half * 2 + cb] + bias[col];
                    if (IS_QKV) {
                        int b_ = row >> 11;
                        int n = row & (NN - 1);
                        int three = col / CC;
                        int rem = col - three * CC;
                        int h = rem >> 6;
                        int hd = rem & 63;
                        int idx = ((b_ * HH + h) * NN + n) * HDIM + hd;
                        if (three == 0)       g_q[idx] = v * SCALE;
                        else if (three == 1)  g_k[idx] = v;
                        else                  g_v[idx] = v;
                    } else {
                        out[row * CC + col] = v;
                    }
                }
            }
        }
    }
}

__global__ __launch_bounds__(256) void qkv_gemm(
    const float* __restrict__ X, const float* __restrict__ W,
    const float* __restrict__ bias)
{
    gemm_body<3 * CC, true>(X, W, bias, nullptr);
}

__global__ __launch_bounds__(256) void proj_gemm(
    const float* __restrict__ W, const float* __restrict__ bias,
    float* __restrict__ out)
{
    gemm_body<CC, false>(g_att, W, bias, out);
}

// ---------------------------------------------------------------------------
// Flash attention with tf32 mma. One CTA = 128 query rows (8 warps x 16 rows),
// KV tiles of 64. P stays in registers (C-frag -> A-frag via shuffles).
// Smem strides 68 floats: Q/K frag reads conflict-free, V reads 2-way.
// ---------------------------------------------------------------------------

#define FP 68

__global__ __launch_bounds__(256) void flash_attn() {
    extern __shared__ uint32_t sm[];
    uint32_t* Qs = sm;                 // [128][68]
    uint32_t* Ks = Qs + 128 * FP;      // [64][68]
    uint32_t* Vs = Ks + 64 * FP;       // [64][68]

    const int tid = threadIdx.x;
    const int warp = tid >> 5;
    const int lane = tid & 31;
    const int g = lane >> 2;
    const int tg = lane & 3;
    const int qbase = warp * 16;

    const int bh = blockIdx.y;
    const int n0 = blockIdx.x * 128;

    const float* __restrict__ Qg = g_q + bh * (NN * HDIM);
    const float* __restrict__ Kg = g_k + bh * (NN * HDIM);
    const float* __restrict__ Vg = g_v + bh * (NN * HDIM);

    // Load Q tile [128][64] -> tf32
    {
        const float4* Qg4 = (const float4*)(Qg + n0 * HDIM);
#pragma unroll
        for (int it = 0; it < 8; it++) {
            int f = tid + it * 256;        // 0..2047
            int row = f >> 4, c4 = (f & 15) * 4;
            float4 v = Qg4[f];
            uint4 u;
            u.x = f2tf32(v.x); u.y = f2tf32(v.y);
            u.z = f2tf32(v.z); u.w = f2tf32(v.w);
            *(uint4*)&Qs[row * FP + c4] = u;
        }
    }

    float m0r = -1e30f, m1r = -1e30f;
    float l0 = 0.f, l1 = 0.f;
    float o[8][4];
#pragma unroll
    for (int nt = 0; nt < 8; nt++)
#pragma unroll
        for (int r = 0; r < 4; r++) o[nt][r] = 0.f;

    const int src0 = (lane & ~3) | (tg >> 1);
    const int src1 = src0 + 2;
    const bool odd = tg & 1;

    for (int j0 = 0; j0 < NN; j0 += 64) {
        __syncthreads();
        // Load K/V tiles [64][64]
        {
            const float4* Kg4 = (const float4*)(Kg + j0 * HDIM);
            const float4* Vg4 = (const float4*)(Vg + j0 * HDIM);
#pragma unroll
            for (int it = 0; it < 4; it++) {
                int f = tid + it * 256;       // 0..1023
                int row = f >> 4, c4 = (f & 15) * 4;
                float4 kv = Kg4[f];
                uint4 uk;
                uk.x = f2tf32(kv.x); uk.y = f2tf32(kv.y);
                uk.z = f2tf32(kv.z); uk.w = f2tf32(kv.w);
                *(uint4*)&Ks[row * FP + c4] = uk;
                float4 vv = Vg4[f];
                uint4 uv;
                uv.x = f2tf32(vv.x); uv.y = f2tf32(vv.y);
                uv.z = f2tf32(vv.z); uv.w = f2tf32(vv.w);
                *(uint4*)&Vs[row * FP + c4] = uv;
            }
        }
        __syncthreads();

        // S = Q @ K^T : s[8][4] C-frags, rows qbase+g / +8, cols nt*8+2tg(+1)
        float s[8][4];
#pragma unroll
        for (int nt = 0; nt < 8; nt++)
#pragma unroll
            for (int r = 0; r < 4; r++) s[nt][r] = 0.f;

#pragma unroll
        for (int kt = 0; kt < 8; kt++) {
            int k0 = kt * 8;
            uint32_t a0 = Qs[(qbase + g) * FP + k0 + tg];
            uint32_t a1 = Qs[(qbase + g + 8) * FP + k0 + tg];
            uint32_t a2 = Qs[(qbase + g) * FP + k0 + tg + 4];
            uint32_t a3 = Qs[(qbase + g + 8) * FP + k0 + tg + 4];
#pragma unroll
            for (int nt = 0; nt < 8; nt++) {
                uint32_t b0 = Ks[(nt * 8 + g) * FP + k0 + tg];
                uint32_t b1 = Ks[(nt * 8 + g) * FP + k0 + tg + 4];
                mma_tf32(s[nt], a0, a1, a2, a3, b0, b1);
            }
        }

        // Online softmax (rows g and g+8; reduce over the 4 quad lanes)
        float tm0 = -1e30f, tm1 = -1e30f;
#pragma unroll
        for (int nt = 0; nt < 8; nt++) {
            tm0 = fmaxf(tm0, fmaxf(s[nt][0], s[nt][1]));
            tm1 = fmaxf(tm1, fmaxf(s[nt][2], s[nt][3]));
        }
        tm0 = fmaxf(tm0, __shfl_xor_sync(0xffffffffu, tm0, 1));
        tm0 = fmaxf(tm0, __shfl_xor_sync(0xffffffffu, tm0, 2));
        tm1 = fmaxf(tm1, __shfl_xor_sync(0xffffffffu, tm1, 1));
        tm1 = fmaxf(tm1, __shfl_xor_sync(0xffffffffu, tm1, 2));

        float nm0 = fmaxf(m0r, tm0), nm1 = fmaxf(m1r, tm1);
        float c0 = __expf(m0r - nm0), c1 = __expf(m1r - nm1);
        float sum0 = 0.f, sum1 = 0.f;
#pragma unroll
        for (int nt = 0; nt < 8; nt++) {
            s[nt][0] = __expf(s[nt][0] - nm0); sum0 += s[nt][0];
            s[nt][1] = __expf(s[nt][1] - nm0); sum0 += s[nt][1];
            s[nt][2] = __expf(s[nt][2] - nm1); sum1 += s[nt][2];
            s[nt][3] = __expf(s[nt][3] - nm1); sum1 += s[nt][3];
        }
        sum0 += __shfl_xor_sync(0xffffffffu, sum0, 1);
        sum0 += __shfl_xor_sync(0xffffffffu, sum0, 2);
        sum1 += __shfl_xor_sync(0xffffffffu, sum1, 1);
        sum1 += __shfl_xor_sync(0xffffffffu, sum1, 2);

        l0 = l0 * c0 + sum0;
        l1 = l1 * c1 + sum1;
        m0r = nm0; m1r = nm1;
#pragma unroll
        for (int nt = 0; nt < 8; nt++) {
            o[nt][0] *= c0; o[nt][1] *= c0;
            o[nt][2] *= c1; o[nt][3] *= c1;
        }

        // O += P @ V  (P C-frags -> A-frags via shuffles)
#pragma unroll
        for (int kt = 0; kt < 8; kt++) {
            float v00 = __shfl_sync(0xffffffffu, s[kt][0], src0);
            float v01 = __shfl_sync(0xffffffffu, s[kt][1], src0);
            float v10 = __shfl_sync(0xffffffffu, s[kt][2], src0);
            float v11 = __shfl_sync(0xffffffffu, s[kt][3], src0);
            float w00 = __shfl_sync(0xffffffffu, s[kt][0], src1);
            float w01 = __shfl_sync(0xffffffffu, s[kt][1], src1);
            float w10 = __shfl_sync(0xffffffffu, s[kt][2], src1);
            float w11 = __shfl_sync(0xffffffffu, s[kt][3], src1);
            uint32_t pa0 = f2tf32(odd ? v01 : v00);
            uint32_t pa1 = f2tf32(odd ? v11 : v10);
            uint32_t pa2 = f2tf32(odd ? w01 : w00);
            uint32_t pa3 = f2tf32(odd ? w11 : w10);
#pragma unroll
            for (int nt = 0; nt < 8; nt++) {
                uint32_t b0 = Vs[(kt * 8 + tg) * FP + nt * 8 + g];
                uint32_t b1 = Vs[(kt * 8 + tg + 4) * FP + nt * 8 + g];
                mma_tf32(o[nt], pa0, pa1, pa2, pa3, b0, b1);
            }
        }
    }

    // Write O / l to g_att in [B, N, C]
    const int b_ = bh / HH;
    const int h = bh % HH;
    float inv0 = 1.f / l0, inv1 = 1.f / l1;
    int row0 = n0 + qbase + g;
    int row1 = row0 + 8;
#pragma unroll
    for (int nt = 0; nt < 8; nt++) {
        int col = h * HDIM + nt * 8 + 2 * tg;
        g_att[(b_ * NN + row0) * CC + col]     = o[nt][0] * inv0;
        g_att[(b_ * NN + row0) * CC + col + 1] = o[nt][1] * inv0;
        g_att[(b_ * NN + row1) * CC + col]     = o[nt][2] * inv1;
        g_att[(b_ * NN + row1) * CC + col + 1] = o[nt][3] * inv1;
    }
}

// ---------------------------------------------------------------------------

extern "C" void kernel_launch(void* const* d_in, const int* in_sizes, int n_in,
                              void* d_out, int out_size) {
    const float* x      = (const float*)d_in[0];
    const float* w_qkv  = (const float*)d_in[1];
    const float* b_qkv  = (const float*)d_in[2];
    const float* w_proj = (const float*)d_in[3];
    const float* b_proj = (const float*)d_in[4];
    float* out = (float*)d_out;

    {
        dim3 grid((3 * CC) / 128, (BB * NN) / 128);  // 18 x 64
        qkv_gemm<<<grid, 256>>>(x, w_qkv, b_qkv);
    }
    {
        int smem = (128 + 64 + 64) * FP * sizeof(uint32_t);  // 69632 B
        cudaFuncSetAttribute(flash_attn, cudaFuncAttributeMaxDynamicSharedMemorySize, smem);
        dim3 grid(NN / 128, BB * HH);  // 16 x 48
        flash_attn<<<grid, 256, smem>>>();
    }
    {
        dim3 grid(CC / 128, (BB * NN) / 128);  // 6 x 64
        proj_gemm<<<grid, 256>>>(w_proj, b_proj, out);
    }
}

// round 4
// speedup vs baseline: 4.1086x; 1.3264x over previous
#include <cuda_runtime.h>
#include <math.h>
#include <stdint.h>

// Problem constants
#define BB 4
#define NN 2048
#define CC 768
#define HH 12
#define HDIM 64
#define SCALE 0.125f   // 64^-0.5

// Scratch (no cudaMalloc allowed -> __device__ globals)
__device__ float g_q[BB * HH * NN * HDIM];     // [B,H,N,HD], pre-scaled
__device__ float g_k[BB * HH * NN * HDIM];
__device__ float g_v[BB * HH * NN * HDIM];
__device__ float g_att[BB * NN * CC];          // attention output, [B,N,C]

__device__ __forceinline__ uint32_t f2tf32(float x) {
    uint32_t r;
    asm("cvt.rna.tf32.f32 %0, %1;" : "=r"(r) : "f"(x));
    return r;
}

__device__ __forceinline__ void mma_tf32(float c[4],
                                         uint32_t a0, uint32_t a1, uint32_t a2, uint32_t a3,
                                         uint32_t b0, uint32_t b1) {
    asm volatile(
        "mma.sync.aligned.m16n8k8.row.col.f32.tf32.tf32.f32 "
        "{%0,%1,%2,%3}, {%4,%5,%6,%7}, {%8,%9}, {%0,%1,%2,%3};"
        : "+f"(c[0]), "+f"(c[1]), "+f"(c[2]), "+f"(c[3])
        : "r"(a0), "r"(a1), "r"(a2), "r"(a3), "r"(b0), "r"(b1));
}

// ---------------------------------------------------------------------------
// tf32 MMA GEMM, CTA tile 128x128, Kstep=16, 8 warps (64x32 each).
// 2-stage ping-pong smem, 1 barrier per k-step, LDG hidden behind MMA.
// ---------------------------------------------------------------------------

#define GP 136

template <int LDW, bool IS_QKV>
__device__ __forceinline__ void gemm_body(
    const float* __restrict__ A,   // [8192, 768] row-major
    const float* __restrict__ W,   // [768, LDW]  row-major
    const float* __restrict__ bias,
    float* __restrict__ out)
{
    __shared__ uint32_t As[2][16][GP];
    __shared__ uint32_t Bs[2][16][GP];

    const int tid = threadIdx.x;
    const int warp = tid >> 5;
    const int lane = tid & 31;
    const int g = lane >> 2;       // 0..7
    const int tg = lane & 3;       // 0..3

    const int m0 = blockIdx.y * 128;
    const int n0 = blockIdx.x * 128;
    const int warp_m = (warp >> 2) * 64;
    const int warp_n = (warp & 3) * 32;

    // Per-thread global-load coordinates (two 512-elt chunks)
    int f0 = tid, f1 = tid + 256;
    const int ar0 = f0 >> 2, ak0 = f0 & 3;
    const int ar1 = f1 >> 2, ak1 = f1 & 3;
    const int bk0 = f0 >> 5, bn0 = f0 & 31;
    const int bk1 = f1 >> 5, bn1 = f1 & 31;

    float acc[4][4][4];
#pragma unroll
    for (int mt = 0; mt < 4; mt++)
#pragma unroll
        for (int nt = 0; nt < 4; nt++)
#pragma unroll
            for (int r = 0; r < 4; r++) acc[mt][nt][r] = 0.f;

    float4 av[2], bv[2];

    // Prologue: load k-step 0, store to stage 0
    av[0] = *(const float4*)&A[(m0 + ar0) * CC + ak0 * 4];
    av[1] = *(const float4*)&A[(m0 + ar1) * CC + ak1 * 4];
    bv[0] = *(const float4*)&W[bk0 * LDW + n0 + bn0 * 4];
    bv[1] = *(const float4*)&W[bk1 * LDW + n0 + bn1 * 4];
    {
        As[0][ak0 * 4 + 0][ar0] = f2tf32(av[0].x);
        As[0][ak0 * 4 + 1][ar0] = f2tf32(av[0].y);
        As[0][ak0 * 4 + 2][ar0] = f2tf32(av[0].z);
        As[0][ak0 * 4 + 3][ar0] = f2tf32(av[0].w);
        As[0][ak1 * 4 + 0][ar1] = f2tf32(av[1].x);
        As[0][ak1 * 4 + 1][ar1] = f2tf32(av[1].y);
        As[0][ak1 * 4 + 2][ar1] = f2tf32(av[1].z);
        As[0][ak1 * 4 + 3][ar1] = f2tf32(av[1].w);
        uint4 bu;
        bu.x = f2tf32(bv[0].x); bu.y = f2tf32(bv[0].y);
        bu.z = f2tf32(bv[0].z); bu.w = f2tf32(bv[0].w);
        *(uint4*)&Bs[0][bk0][bn0 * 4] = bu;
        bu.x = f2tf32(bv[1].x); bu.y = f2tf32(bv[1].y);
        bu.z = f2tf32(bv[1].z); bu.w = f2tf32(bv[1].w);
        *(uint4*)&Bs[0][bk1][bn1 * 4] = bu;
    }
    __syncthreads();

    const int NSTEP = CC / 16;   // 48
    for (int ks = 0; ks < NSTEP; ks++) {
        const int st = ks & 1;
        const bool more = (ks + 1 < NSTEP);
        if (more) {
            int k0 = (ks + 1) * 16;
            av[0] = *(const float4*)&A[(m0 + ar0) * CC + k0 + ak0 * 4];
            av[1] = *(const float4*)&A[(m0 + ar1) * CC + k0 + ak1 * 4];
            bv[0] = *(const float4*)&W[(k0 + bk0) * LDW + n0 + bn0 * 4];
            bv[1] = *(const float4*)&W[(k0 + bk1) * LDW + n0 + bn1 * 4];
        }

#pragma unroll
        for (int kk = 0; kk < 16; kk += 8) {
            uint32_t a[4][4], b[4][2];
#pragma unroll
            for (int mt = 0; mt < 4; mt++) {
                int mr = warp_m + mt * 16 + g;
                a[mt][0] = As[st][kk + tg][mr];
                a[mt][1] = As[st][kk + tg][mr + 8];
                a[mt][2] = As[st][kk + tg + 4][mr];
                a[mt][3] = As[st][kk + tg + 4][mr + 8];
            }
#pragma unroll
            for (int nt = 0; nt < 4; nt++) {
                int nc = warp_n + nt * 8 + g;
                b[nt][0] = Bs[st][kk + tg][nc];
                b[nt][1] = Bs[st][kk + tg + 4][nc];
            }
#pragma unroll
            for (int mt = 0; mt < 4; mt++)
#pragma unroll
                for (int nt = 0; nt < 4; nt++)
                    mma_tf32(acc[mt][nt], a[mt][0], a[mt][1], a[mt][2], a[mt][3],
                             b[nt][0], b[nt][1]);
        }

        if (more) {
            const int sn = st ^ 1;
            As[sn][ak0 * 4 + 0][ar0] = f2tf32(av[0].x);
            As[sn][ak0 * 4 + 1][ar0] = f2tf32(av[0].y);
            As[sn][ak0 * 4 + 2][ar0] = f2tf32(av[0].z);
            As[sn][ak0 * 4 + 3][ar0] = f2tf32(av[0].w);
            As[sn][ak1 * 4 + 0][ar1] = f2tf32(av[1].x);
            As[sn][ak1 * 4 + 1][ar1] = f2tf32(av[1].y);
            As[sn][ak1 * 4 + 2][ar1] = f2tf32(av[1].z);
            As[sn][ak1 * 4 + 3][ar1] = f2tf32(av[1].w);
            uint4 bu;
            bu.x = f2tf32(bv[0].x); bu.y = f2tf32(bv[0].y);
            bu.z = f2tf32(bv[0].z); bu.w = f2tf32(bv[0].w);
            *(uint4*)&Bs[sn][bk0][bn0 * 4] = bu;
            bu.x = f2tf32(bv[1].x); bu.y = f2tf32(bv[1].y);
            bu.z = f2tf32(bv[1].z); bu.w = f2tf32(bv[1].w);
            *(uint4*)&Bs[sn][bk1][bn1 * 4] = bu;
        }
        __syncthreads();
    }

    // Epilogue
#pragma unroll
    for (int mt = 0; mt < 4; mt++) {
#pragma unroll
        for (int nt = 0; nt < 4; nt++) {
#pragma unroll
            for (int half = 0; half < 2; half++) {
                int row = m0 + warp_m + mt * 16 + g + half * 8;
#pragma unroll
                for (int cb = 0; cb < 2; cb++) {
                    int col = n0 + warp_n + nt * 8 + 2 * tg + cb;
                    float v = acc[mt][nt][half * 2 + cb] + bias[col];
                    if (IS_QKV) {
                        int b_ = row >> 11;
                        int n = row & (NN - 1);
                        int three = col / CC;
                        int rem = col - three * CC;
                        int h = rem >> 6;
                        int hd = rem & 63;
                        int idx = ((b_ * HH + h) * NN + n) * HDIM + hd;
                        if (three == 0)       g_q[idx] = v * SCALE;
                        else if (three == 1)  g_k[idx] = v;
                        else                  g_v[idx] = v;
                    } else {
                        out[row * CC + col] = v;
                    }
                }
            }
        }
    }
}

__global__ __launch_bounds__(256, 2) void qkv_gemm(
    const float* __restrict__ X, const float* __restrict__ W,
    const float* __restrict__ bias)
{
    gemm_body<3 * CC, true>(X, W, bias, nullptr);
}

__global__ __launch_bounds__(256, 2) void proj_gemm(
    const float* __restrict__ W, const float* __restrict__ bias,
    float* __restrict__ out)
{
    gemm_body<CC, false>(g_att, W, bias, out);
}

// ---------------------------------------------------------------------------
// Flash attention, tf32 mma. One CTA = 256 query rows (8 warps x 32 rows),
// KV tiles of 64. Software-pipelined K/V loads. P stays in registers.
// Qs/Ks pitch 68 (conflict-free), Vs pitch 72 (conflict-free).
// ---------------------------------------------------------------------------

#define FPQ 68
#define FPV 72
#define QT 256

__global__ __launch_bounds__(256, 1) void flash_attn() {
    extern __shared__ uint32_t sm[];
    uint32_t* Qs = sm;                   // [256][68]
    uint32_t* Ks = Qs + QT * FPQ;        // [64][68]
    uint32_t* Vs = Ks + 64 * FPQ;        // [64][72]

    const int tid = threadIdx.x;
    const int warp = tid >> 5;
    const int lane = tid & 31;
    const int g = lane >> 2;
    const int tg = lane & 3;
    const int qbase = warp * 32;

    const int bh = blockIdx.y;
    const int n0 = blockIdx.x * QT;

    const float* __restrict__ Qg = g_q + bh * (NN * HDIM);
    const float* __restrict__ Kg = g_k + bh * (NN * HDIM);
    const float* __restrict__ Vg = g_v + bh * (NN * HDIM);

    // Per-thread K/V tile load coords: f = tid + it*256, it<4
    const int ldrow[4] = { tid >> 4, (tid + 256) >> 4, (tid + 512) >> 4, (tid + 768) >> 4 };
    const int ldc4 = (tid & 15) * 4;

    // Load Q tile [256][64] -> tf32
    {
        const float4* Qg4 = (const float4*)(Qg + n0 * HDIM);
#pragma unroll
        for (int it = 0; it < 16; it++) {
            int f = tid + it * 256;
            int row = f >> 4, c4 = (f & 15) * 4;
            float4 v = Qg4[f];
            uint4 u;
            u.x = f2tf32(v.x); u.y = f2tf32(v.y);
            u.z = f2tf32(v.z); u.w = f2tf32(v.w);
            *(uint4*)&Qs[row * FPQ + c4] = u;
        }
    }

    float mR[2][2], lR[2][2];
    float o[2][8][4];
#pragma unroll
    for (int mt = 0; mt < 2; mt++) {
        mR[mt][0] = -1e30f; mR[mt][1] = -1e30f;
        lR[mt][0] = 0.f; lR[mt][1] = 0.f;
#pragma unroll
        for (int nt = 0; nt < 8; nt++)
#pragma unroll
            for (int r = 0; r < 4; r++) o[mt][nt][r] = 0.f;
    }

    const int src0 = (lane & ~3) | (tg >> 1);
    const int src1 = src0 + 2;
    const bool odd = tg & 1;

    // Prologue: prefetch K(0)
    float4 kreg[4], vreg[4];
#pragma unroll
    for (int it = 0; it < 4; it++)
        kreg[it] = ((const float4*)Kg)[tid + it * 256];

    for (int j0 = 0; j0 < NN; j0 += 64) {
        // Store K tile (prefetched) to smem
#pragma unroll
        for (int it = 0; it < 4; it++) {
            uint4 u;
            u.x = f2tf32(kreg[it].x); u.y = f2tf32(kreg[it].y);
            u.z = f2tf32(kreg[it].z); u.w = f2tf32(kreg[it].w);
            *(uint4*)&Ks[ldrow[it] * FPQ + ldc4] = u;
        }
        // Launch V loads (consumed after softmax)
#pragma unroll
        for (int it = 0; it < 4; it++)
            vreg[it] = ((const float4*)(Vg + j0 * HDIM))[tid + it * 256];
        __syncthreads();

        // S = Q @ K^T : s[2][8][4]
        float s[2][8][4];
#pragma unroll
        for (int mt = 0; mt < 2; mt++)
#pragma unroll
            for (int nt = 0; nt < 8; nt++)
#pragma unroll
                for (int r = 0; r < 4; r++) s[mt][nt][r] = 0.f;

#pragma unroll
        for (int kt = 0; kt < 8; kt++) {
            int k0 = kt * 8;
            uint32_t a[2][4];
#pragma unroll
            for (int mt = 0; mt < 2; mt++) {
                int row = qbase + mt * 16 + g;
                a[mt][0] = Qs[row * FPQ + k0 + tg];
                a[mt][1] = Qs[(row + 8) * FPQ + k0 + tg];
                a[mt][2] = Qs[row * FPQ + k0 + tg + 4];
                a[mt][3] = Qs[(row + 8) * FPQ + k0 + tg + 4];
            }
#pragma unroll
            for (int nt = 0; nt < 8; nt++) {
                uint32_t b0 = Ks[(nt * 8 + g) * FPQ + k0 + tg];
                uint32_t b1 = Ks[(nt * 8 + g) * FPQ + k0 + tg + 4];
                mma_tf32(s[0][nt], a[0][0], a[0][1], a[0][2], a[0][3], b0, b1);
                mma_tf32(s[1][nt], a[1][0], a[1][1], a[1][2], a[1][3], b0, b1);
            }
        }

        // Online softmax per mt (rows g and g+8; reduce over 4 quad lanes)
#pragma unroll
        for (int mt = 0; mt < 2; mt++) {
            float tm0 = -1e30f, tm1 = -1e30f;
#pragma unroll
            for (int nt = 0; nt < 8; nt++) {
                tm0 = fmaxf(tm0, fmaxf(s[mt][nt][0], s[mt][nt][1]));
                tm1 = fmaxf(tm1, fmaxf(s[mt][nt][2], s[mt][nt][3]));
            }
            tm0 = fmaxf(tm0, __shfl_xor_sync(0xffffffffu, tm0, 1));
            tm0 = fmaxf(tm0, __shfl_xor_sync(0xffffffffu, tm0, 2));
            tm1 = fmaxf(tm1, __shfl_xor_sync(0xffffffffu, tm1, 1));
            tm1 = fmaxf(tm1, __shfl_xor_sync(0xffffffffu, tm1, 2));

            float nm0 = fmaxf(mR[mt][0], tm0), nm1 = fmaxf(mR[mt][1], tm1);
            float c0 = __expf(mR[mt][0] - nm0), c1 = __expf(mR[mt][1] - nm1);
            float sum0 = 0.f, sum1 = 0.f;
#pragma unroll
            for (int nt = 0; nt < 8; nt++) {
                s[mt][nt][0] = __expf(s[mt][nt][0] - nm0); sum0 += s[mt][nt][0];
                s[mt][nt][1] = __expf(s[mt][nt][1] - nm0); sum0 += s[mt][nt][1];
                s[mt][nt][2] = __expf(s[mt][nt][2] - nm1); sum1 += s[mt][nt][2];
                s[mt][nt][3] = __expf(s[mt][nt][3] - nm1); sum1 += s[mt][nt][3];
            }
            sum0 += __shfl_xor_sync(0xffffffffu, sum0, 1);
            sum0 += __shfl_xor_sync(0xffffffffu, sum0, 2);
            sum1 += __shfl_xor_sync(0xffffffffu, sum1, 1);
            sum1 += __shfl_xor_sync(0xffffffffu, sum1, 2);

            lR[mt][0] = lR[mt][0] * c0 + sum0;
            lR[mt][1] = lR[mt][1] * c1 + sum1;
            mR[mt][0] = nm0; mR[mt][1] = nm1;
#pragma unroll
            for (int nt = 0; nt < 8; nt++) {
                o[mt][nt][0] *= c0; o[mt][nt][1] *= c0;
                o[mt][nt][2] *= c1; o[mt][nt][3] *= c1;
            }
        }

        // Store V tile, prefetch next K
#pragma unroll
        for (int it = 0; it < 4; it++) {
            uint4 u;
            u.x = f2tf32(vreg[it].x); u.y = f2tf32(vreg[it].y);
            u.z = f2tf32(vreg[it].z); u.w = f2tf32(vreg[it].w);
            *(uint4*)&Vs[ldrow[it] * FPV + ldc4] = u;
        }
        if (j0 + 64 < NN) {
#pragma unroll
            for (int it = 0; it < 4; it++)
                kreg[it] = ((const float4*)(Kg + (j0 + 64) * HDIM))[tid + it * 256];
        }
        __syncthreads();

        // O += P @ V  (P C-frags -> A-frags via shuffles; b-frags shared over mt)
#pragma unroll
        for (int kt = 0; kt < 8; kt++) {
            uint32_t b0[8], b1[8];
#pragma unroll
            for (int nt = 0; nt < 8; nt++) {
                b0[nt] = Vs[(kt * 8 + tg) * FPV + nt * 8 + g];
                b1[nt] = Vs[(kt * 8 + tg + 4) * FPV + nt * 8 + g];
            }
#pragma unroll
            for (int mt = 0; mt < 2; mt++) {
                float v00 = __shfl_sync(0xffffffffu, s[mt][kt][0], src0);
                float v01 = __shfl_sync(0xffffffffu, s[mt][kt][1], src0);
                float v10 = __shfl_sync(0xffffffffu, s[mt][kt][2], src0);
                float v11 = __shfl_sync(0xffffffffu, s[mt][kt][3], src0);
                float w00 = __shfl_sync(0xffffffffu, s[mt][kt][0], src1);
                float w01 = __shfl_sync(0xffffffffu, s[mt][kt][1], src1);
                float w10 = __shfl_sync(0xffffffffu, s[mt][kt][2], src1);
                float w11 = __shfl_sync(0xffffffffu, s[mt][kt][3], src1);
                uint32_t pa0 = f2tf32(odd ? v01 : v00);
                uint32_t pa1 = f2tf32(odd ? v11 : v10);
                uint32_t pa2 = f2tf32(odd ? w01 : w00);
                uint32_t pa3 = f2tf32(odd ? w11 : w10);
#pragma unroll
                for (int nt = 0; nt < 8; nt++)
                    mma_tf32(o[mt][nt], pa0, pa1, pa2, pa3, b0[nt], b1[nt]);
            }
        }
    }

    // Write O / l to g_att in [B, N, C]
    const int b_ = bh / HH;
    const int h = bh % HH;
#pragma unroll
    for (int mt = 0; mt < 2; mt++) {
        float inv0 = 1.f / lR[mt][0], inv1 = 1.f / lR[mt][1];
        int row0 = n0 + qbase + mt * 16 + g;
        int row1 = row0 + 8;
#pragma unroll
        for (int nt = 0; nt < 8; nt++) {
            int col = h * HDIM + nt * 8 + 2 * tg;
            float2 p0 = make_float2(o[mt][nt][0] * inv0, o[mt][nt][1] * inv0);
            float2 p1 = make_float2(o[mt][nt][2] * inv1, o[mt][nt][3] * inv1);
            *(float2*)&g_att[(b_ * NN + row0) * CC + col] = p0;
            *(float2*)&g_att[(b_ * NN + row1) * CC + col] = p1;
        }
    }
}

// ---------------------------------------------------------------------------

extern "C" void kernel_launch(void* const* d_in, const int* in_sizes, int n_in,
                              void* d_out, int out_size) {
    const float* x      = (const float*)d_in[0];
    const float* w_qkv  = (const float*)d_in[1];
    const float* b_qkv  = (const float*)d_in[2];
    const float* w_proj = (const float*)d_in[3];
    const float* b_proj = (const float*)d_in[4];
    float* out = (float*)d_out;

    {
        dim3 grid((3 * CC) / 128, (BB * NN) / 128);  // 18 x 64
        qkv_gemm<<<grid, 256>>>(x, w_qkv, b_qkv);
    }
    {
        int smem = (QT * FPQ + 64 * FPQ + 64 * FPV) * sizeof(uint32_t);  // 105472 B
        cudaFuncSetAttribute(flash_attn, cudaFuncAttributeMaxDynamicSharedMemorySize, smem);
        dim3 grid(NN / QT, BB * HH);  // 8 x 48
        flash_attn<<<grid, 256, smem>>>();
    }
    {
        dim3 grid(CC / 128, (BB * NN) / 128);  // 6 x 64
        proj_gemm<<<grid, 256>>>(w_proj, b_proj, out);
    }
}

// round 6
// speedup vs baseline: 6.9048x; 1.6806x over previous
#include <cuda_runtime.h>
#include <cuda_fp16.h>
#include <math.h>
#include <stdint.h>

// Problem constants
#define BB 4
#define NN 2048
#define CC 768
#define HH 12
#define HDIM 64
#define SCALE 0.125f   // 64^-0.5

// Scratch (no cudaMalloc allowed -> __device__ globals)
__device__ float g_q[BB * HH * NN * HDIM];     // [B,H,N,HD], pre-scaled
__device__ float g_k[BB * HH * NN * HDIM];
__device__ float g_v[BB * HH * NN * HDIM];
__device__ float g_att[BB * NN * CC];          // attention output, [B,N,C]

// ---------------------------------------------------------------------------
// Helpers
// ---------------------------------------------------------------------------

__device__ __forceinline__ uint32_t smem_u32(const void* p) {
    uint32_t a;
    asm("{ .reg .u64 t; cvta.to.shared.u64 t, %1; cvt.u32.u64 %0, t; }" : "=r"(a) : "l"(p));
    return a;
}

// pack two f32 into f16x2: low half = lo, high half = hi
__device__ __forceinline__ uint32_t packh2(float lo, float hi) {
    uint32_t r;
    asm("cvt.rn.f16x2.f32 %0, %1, %2;" : "=r"(r) : "f"(hi), "f"(lo));
    return r;
}

__device__ __forceinline__ void mma_f16(float c[4],
                                        uint32_t a0, uint32_t a1, uint32_t a2, uint32_t a3,
                                        uint32_t b0, uint32_t b1) {
    asm volatile(
        "mma.sync.aligned.m16n8k16.row.col.f32.f16.f16.f32 "
        "{%0,%1,%2,%3}, {%4,%5,%6,%7}, {%8,%9}, {%0,%1,%2,%3};"
        : "+f"(c[0]), "+f"(c[1]), "+f"(c[2]), "+f"(c[3])
        : "r"(a0), "r"(a1), "r"(a2), "r"(a3), "r"(b0), "r"(b1));
}

__device__ __forceinline__ void ldsm_x4(uint32_t& r0, uint32_t& r1, uint32_t& r2, uint32_t& r3,
                                        uint32_t a) {
    asm volatile("ldmatrix.sync.aligned.m8n8.x4.shared.b16 {%0,%1,%2,%3}, [%4];"
                 : "=r"(r0), "=r"(r1), "=r"(r2), "=r"(r3) : "r"(a));
}
__device__ __forceinline__ void ldsm_x2(uint32_t& r0, uint32_t& r1, uint32_t a) {
    asm volatile("ldmatrix.sync.aligned.m8n8.x2.shared.b16 {%0,%1}, [%2];"
                 : "=r"(r0), "=r"(r1) : "r"(a));
}
__device__ __forceinline__ void ldsm_x2t(uint32_t& r0, uint32_t& r1, uint32_t a) {
    asm volatile("ldmatrix.sync.aligned.m8n8.x2.trans.shared.b16 {%0,%1}, [%2];"
                 : "=r"(r0), "=r"(r1) : "r"(a));
}

// ---------------------------------------------------------------------------
// fp16 MMA GEMM: CTA 128x128, Kstep=32, 8 warps (64x32 each), 2-stage pipeline.
// As [m][k] pitch 40 halfs; Bs [k][n] pitch 136 halfs. ldmatrix fragment loads.
// ---------------------------------------------------------------------------

#define APITCH 40
#define BPITCH 136

template <int LDW, bool IS_QKV>
__device__ __forceinline__ void gemm_body(
    const float* __restrict__ A,   // [8192, CC] row-major
    const float* __restrict__ W,   // [CC, LDW]  row-major
    const float* __restrict__ bias,
    float* __restrict__ out)
{
    __shared__ __half As[2][128 * APITCH];
    __shared__ __half Bs[2][32 * BPITCH];

    const int tid = threadIdx.x;
    const int warp = tid >> 5;
    const int lane = tid & 31;
    const int g = lane >> 2;
    const int tg = lane & 3;

    const int m0 = blockIdx.y * 128;
    const int n0 = blockIdx.x * 128;
    const int warp_m = (warp >> 2) * 64;
    const int warp_n = (warp & 3) * 32;

    // ldmatrix per-lane address components
    const int a_row_off = (lane & 7) + 8 * ((lane >> 3) & 1);
    const int a_col_off = 8 * (lane >> 4);
    const int b_row_off = lane & 15;

    const uint32_t asb[2] = { smem_u32(&As[0][0]), smem_u32(&As[1][0]) };
    const uint32_t bsb[2] = { smem_u32(&Bs[0][0]), smem_u32(&Bs[1][0]) };

    // Global load coords: f = tid + it*256, it<4
    int am[4], ak4[4], bk[4], bn4[4];
#pragma unroll
    for (int it = 0; it < 4; it++) {
        int f = tid + it * 256;
        am[it] = f >> 3;  ak4[it] = f & 7;    // A: 128 rows x 8 float4
        bk[it] = f >> 5;  bn4[it] = f & 31;   // B: 32 rows x 32 float4
    }

    float acc[4][4][4];
#pragma unroll
    for (int mt = 0; mt < 4; mt++)
#pragma unroll
        for (int nt = 0; nt < 4; nt++)
#pragma unroll
            for (int r = 0; r < 4; r++) acc[mt][nt][r] = 0.f;

    float4 av[4], bv[4];

#pragma unroll
    for (int it = 0; it < 4; it++) {
        av[it] = *(const float4*)&A[(m0 + am[it]) * CC + ak4[it] * 4];
        bv[it] = *(const float4*)&W[bk[it] * LDW + n0 + bn4[it] * 4];
    }
#pragma unroll
    for (int it = 0; it < 4; it++) {
        uint2 ua = make_uint2(packh2(av[it].x, av[it].y), packh2(av[it].z, av[it].w));
        *(uint2*)&As[0][am[it] * APITCH + ak4[it] * 4] = ua;
        uint2 ub = make_uint2(packh2(bv[it].x, bv[it].y), packh2(bv[it].z, bv[it].w));
        *(uint2*)&Bs[0][bk[it] * BPITCH + bn4[it] * 4] = ub;
    }
    __syncthreads();

    const int NSTEP = CC / 32;  // 24
    for (int ks = 0; ks < NSTEP; ks++) {
        const int b = ks & 1;
        const bool more = (ks + 1 < NSTEP);
        if (more) {
            int k0 = (ks + 1) * 32;
#pragma unroll
            for (int it = 0; it < 4; it++) {
                av[it] = *(const float4*)&A[(m0 + am[it]) * CC + k0 + ak4[it] * 4];
                bv[it] = *(const float4*)&W[(k0 + bk[it]) * LDW + n0 + bn4[it] * 4];
            }
        }

#pragma unroll
        for (int kc = 0; kc < 2; kc++) {
            uint32_t a[4][4], b0[4], b1[4];
#pragma unroll
            for (int mt = 0; mt < 4; mt++)
                ldsm_x4(a[mt][0], a[mt][1], a[mt][2], a[mt][3],
                        asb[b] + ((warp_m + mt * 16 + a_row_off) * APITCH + kc * 16 + a_col_off) * 2);
#pragma unroll
            for (int nt = 0; nt < 4; nt++)
                ldsm_x2t(b0[nt], b1[nt],
                         bsb[b] + ((kc * 16 + b_row_off) * BPITCH + warp_n + nt * 8) * 2);
#pragma unroll
            for (int mt = 0; mt < 4; mt++)
#pragma unroll
                for (int nt = 0; nt < 4; nt++)
                    mma_f16(acc[mt][nt], a[mt][0], a[mt][1], a[mt][2], a[mt][3],
                            b0[nt], b1[nt]);
        }

        if (more) {
            const int sn = b ^ 1;
#pragma unroll
            for (int it = 0; it < 4; it++) {
                uint2 ua = make_uint2(packh2(av[it].x, av[it].y), packh2(av[it].z, av[it].w));
                *(uint2*)&As[sn][am[it] * APITCH + ak4[it] * 4] = ua;
                uint2 ub = make_uint2(packh2(bv[it].x, bv[it].y), packh2(bv[it].z, bv[it].w));
                *(uint2*)&Bs[sn][bk[it] * BPITCH + bn4[it] * 4] = ub;
            }
        }
        __syncthreads();
    }

    // Epilogue
#pragma unroll
    for (int mt = 0; mt < 4; mt++) {
#pragma unroll
        for (int nt = 0; nt < 4; nt++) {
#pragma unroll
            for (int half = 0; half < 2; half++) {
                int row = m0 + warp_m + mt * 16 + g + half * 8;
#pragma unroll
                for (int cb = 0; cb < 2; cb++) {
                    int col = n0 + warp_n + nt * 8 + 2 * tg + cb;
                    float v = acc[mt][nt][half * 2 + cb] + bias[col];
                    if (IS_QKV) {
                        int b_ = row >> 11;
                        int n = row & (NN - 1);
                        int three = col / CC;
                        int rem = col - three * CC;
                        int h = rem >> 6;
                        int hd = rem & 63;
                        int idx = ((b_ * HH + h) * NN + n) * HDIM + hd;
                        if (three == 0)       g_q[idx] = v * SCALE;
                        else if (three == 1)  g_k[idx] = v;
                        else                  g_v[idx] = v;
                    } else {
                        out[row * CC + col] = v;
                    }
                }
            }
        }
    }
}

__global__ __launch_bounds__(256, 2) void qkv_gemm(
    const float* __restrict__ X, const float* __restrict__ W,
    const float* __restrict__ bias)
{
    gemm_body<3 * CC, true>(X, W, bias, nullptr);
}

__global__ __launch_bounds__(256, 2) void proj_gemm(
    const float* __restrict__ W, const float* __restrict__ bias,
    float* __restrict__ out)
{
    gemm_body<CC, false>(g_att, W, bias, out);
}

// ---------------------------------------------------------------------------
// Flash attention, fp16 mma m16n8k16. One CTA = 256 query rows (8 warps x 32),
// KV tiles of 64. Q fragments hoisted into registers. P C-frag == A-frag
// layout (no shuffles). All frags via ldmatrix; pitch 72 halfs conflict-free.
// ---------------------------------------------------------------------------

#define FPH 72
#define QT 256

__global__ __launch_bounds__(256, 1) void flash_attn() {
    extern __shared__ __half fsm[];
    __half* Qs = fsm;                    // [256][72]
    __half* Ks = Qs + QT * FPH;          // [64][72]
    __half* Vs = Ks + 64 * FPH;          // [64][72]

    const int tid = threadIdx.x;
    const int warp = tid >> 5;
    const int lane = tid & 31;
    const int g = lane >> 2;
    const int tg = lane & 3;
    const int qbase = warp * 32;

    const int bh = blockIdx.y;
    const int n0 = blockIdx.x * QT;

    const float* __restrict__ Qg = g_q + bh * (NN * HDIM);
    const float* __restrict__ Kg = g_k + bh * (NN * HDIM);
    const float* __restrict__ Vg = g_v + bh * (NN * HDIM);

    const uint32_t qsb = smem_u32(Qs);
    const uint32_t ksb = smem_u32(Ks);
    const uint32_t vsb = smem_u32(Vs);

    // ldmatrix per-lane address components
    const int a_row_off = (lane & 7) + 8 * ((lane >> 3) & 1);
    const int a_col_off = 8 * (lane >> 4);
    const int k_row_off = lane & 7;              // + nt*8
    const int k_col_off = 8 * ((lane >> 3) & 1); // + kc*16
    const int v_row_off = lane & 15;             // + kc*16

    // K/V tile load coords (64 rows x 16 float4)
    const int ldrow[4] = { tid >> 4, (tid + 256) >> 4, (tid + 512) >> 4, (tid + 768) >> 4 };
    const int ldc4 = (tid & 15) * 4;

    // Load Q tile [256][64] -> f16 smem
    {
        const float4* Qg4 = (const float4*)(Qg + n0 * HDIM);
#pragma unroll
        for (int it = 0; it < 16; it++) {
            int f = tid + it * 256;
            int row = f >> 4, c4 = (f & 15) * 4;
            float4 v = Qg4[f];
            uint2 u = make_uint2(packh2(v.x, v.y), packh2(v.z, v.w));
            *(uint2*)&Qs[row * FPH + c4] = u;
        }
    }
    __syncthreads();

    // Hoist Q fragments into registers (loop-invariant): qa[mt][kc][4]
    uint32_t qa[2][4][4];
#pragma unroll
    for (int mt = 0; mt < 2; mt++)
#pragma unroll
        for (int kc = 0; kc < 4; kc++)
            ldsm_x4(qa[mt][kc][0], qa[mt][kc][1], qa[mt][kc][2], qa[mt][kc][3],
                    qsb + ((qbase + mt * 16 + a_row_off) * FPH + kc * 16 + a_col_off) * 2);

    float mR[2][2], lR[2][2];
    float o[2][8][4];
#pragma unroll
    for (int mt = 0; mt < 2; mt++) {
        mR[mt][0] = -1e30f; mR[mt][1] = -1e30f;
        lR[mt][0] = 0.f; lR[mt][1] = 0.f;
#pragma unroll
        for (int nt = 0; nt < 8; nt++)
#pragma unroll
            for (int r = 0; r < 4; r++) o[mt][nt][r] = 0.f;
    }

    float4 kreg[4], vreg[4];
#pragma unroll
    for (int it = 0; it < 4; it++)
        kreg[it] = ((const float4*)Kg)[tid + it * 256];

    for (int j0 = 0; j0 < NN; j0 += 64) {
        // Store K tile (prefetched), issue V loads
#pragma unroll
        for (int it = 0; it < 4; it++) {
            uint2 u = make_uint2(packh2(kreg[it].x, kreg[it].y), packh2(kreg[it].z, kreg[it].w));
            *(uint2*)&Ks[ldrow[it] * FPH + ldc4] = u;
        }
#pragma unroll
        for (int it = 0; it < 4; it++)
            vreg[it] = ((const float4*)(Vg + j0 * HDIM))[tid + it * 256];
        __syncthreads();

        // S = Q @ K^T : s[2][8][4]
        float s[2][8][4];
#pragma unroll
        for (int mt = 0; mt < 2; mt++)
#pragma unroll
            for (int nt = 0; nt < 8; nt++)
#pragma unroll
                for (int r = 0; r < 4; r++) s[mt][nt][r] = 0.f;

#pragma unroll
        for (int kc = 0; kc < 4; kc++) {
#pragma unroll
            for (int nt = 0; nt < 8; nt++) {
                uint32_t b0, b1;
                ldsm_x2(b0, b1,
                        ksb + ((nt * 8 + k_row_off) * FPH + kc * 16 + k_col_off) * 2);
                mma_f16(s[0][nt], qa[0][kc][0], qa[0][kc][1], qa[0][kc][2], qa[0][kc][3], b0, b1);
                mma_f16(s[1][nt], qa[1][kc][0], qa[1][kc][1], qa[1][kc][2], qa[1][kc][3], b0, b1);
            }
        }

        // Online softmax
#pragma unroll
        for (int mt = 0; mt < 2; mt++) {
            float tm0 = -1e30f, tm1 = -1e30f;
#pragma unroll
            for (int nt = 0; nt < 8; nt++) {
                tm0 = fmaxf(tm0, fmaxf(s[mt][nt][0], s[mt][nt][1]));
                tm1 = fmaxf(tm1, fmaxf(s[mt][nt][2], s[mt][nt][3]));
            }
            tm0 = fmaxf(tm0, __shfl_xor_sync(0xffffffffu, tm0, 1));
            tm0 = fmaxf(tm0, __shfl_xor_sync(0xffffffffu, tm0, 2));
            tm1 = fmaxf(tm1, __shfl_xor_sync(0xffffffffu, tm1, 1));
            tm1 = fmaxf(tm1, __shfl_xor_sync(0xffffffffu, tm1, 2));

            float nm0 = fmaxf(mR[mt][0], tm0), nm1 = fmaxf(mR[mt][1], tm1);
            float c0 = __expf(mR[mt][0] - nm0), c1 = __expf(mR[mt][1] - nm1);
            float sum0 = 0.f, sum1 = 0.f;
#pragma unroll
            for (int nt = 0; nt < 8; nt++) {
                s[mt][nt][0] = __expf(s[mt][nt][0] - nm0); sum0 += s[mt][nt][0];
                s[mt][nt][1] = __expf(s[mt][nt][1] - nm0); sum0 += s[mt][nt][1];
                s[mt][nt][2] = __expf(s[mt][nt][2] - nm1); sum1 += s[mt][nt][2];
                s[mt][nt][3] = __expf(s[mt][nt][3] - nm1); sum1 += s[mt][nt][3];
            }
            sum0 += __shfl_xor_sync(0xffffffffu, sum0, 1);
            sum0 += __shfl_xor_sync(0xffffffffu, sum0, 2);
            sum1 += __shfl_xor_sync(0xffffffffu, sum1, 1);
            sum1 += __shfl_xor_sync(0xffffffffu, sum1, 2);

            lR[mt][0] = lR[mt][0] * c0 + sum0;
            lR[mt][1] = lR[mt][1] * c1 + sum1;
            mR[mt][0] = nm0; mR[mt][1] = nm1;
#pragma unroll
            for (int nt = 0; nt < 8; nt++) {
                o[mt][nt][0] *= c0; o[mt][nt][1] *= c0;
                o[mt][nt][2] *= c1; o[mt][nt][3] *= c1;
            }
        }

        // Store V tile, prefetch next K
#pragma unroll
        for (int it = 0; it < 4; it++) {
            uint2 u = make_uint2(packh2(vreg[it].x, vreg[it].y), packh2(vreg[it].z, vreg[it].w));
            *(uint2*)&Vs[ldrow[it] * FPH + ldc4] = u;
        }
        if (j0 + 64 < NN) {
#pragma unroll
            for (int it = 0; it < 4; it++)
                kreg[it] = ((const float4*)(Kg + (j0 + 64) * HDIM))[tid + it * 256];
        }
        __syncthreads();

        // O += P @ V   (P A-frags packed straight from S C-frags)
#pragma unroll
        for (int kc = 0; kc < 4; kc++) {
            uint32_t pa[2][4];
#pragma unroll
            for (int mt = 0; mt < 2; mt++) {
                pa[mt][0] = packh2(s[mt][2 * kc][0],     s[mt][2 * kc][1]);
                pa[mt][1] = packh2(s[mt][2 * kc][2],     s[mt][2 * kc][3]);
                pa[mt][2] = packh2(s[mt][2 * kc + 1][0], s[mt][2 * kc + 1][1]);
                pa[mt][3] = packh2(s[mt][2 * kc + 1][2], s[mt][2 * kc + 1][3]);
            }
#pragma unroll
            for (int nt = 0; nt < 8; nt++) {
                uint32_t b0, b1;
                ldsm_x2t(b0, b1, vsb + ((kc * 16 + v_row_off) * FPH + nt * 8) * 2);
                mma_f16(o[0][nt], pa[0][0], pa[0][1], pa[0][2], pa[0][3], b0, b1);
                mma_f16(o[1][nt], pa[1][0], pa[1][1], pa[1][2], pa[1][3], b0, b1);
            }
        }
    }

    // Write O / l to g_att in [B, N, C]
    const int b_ = bh / HH;
    const int h = bh % HH;
#pragma unroll
    for (int mt = 0; mt < 2; mt++) {
        float inv0 = 1.f / lR[mt][0], inv1 = 1.f / lR[mt][1];
        int row0 = n0 + qbase + mt * 16 + g;
        int row1 = row0 + 8;
#pragma unroll
        for (int nt = 0; nt < 8; nt++) {
            int col = h * HDIM + nt * 8 + 2 * tg;
            float2 p0 = make_float2(o[mt][nt][0] * inv0, o[mt][nt][1] * inv0);
            float2 p1 = make_float2(o[mt][nt][2] * inv1, o[mt][nt][3] * inv1);
            *(float2*)&g_att[(b_ * NN + row0) * CC + col] = p0;
            *(float2*)&g_att[(b_ * NN + row1) * CC + col] = p1;
        }
    }
}

// ---------------------------------------------------------------------------

extern "C" void kernel_launch(void* const* d_in, const int* in_sizes, int n_in,
                              void* d_out, int out_size) {
    const float* x      = (const float*)d_in[0];
    const float* w_qkv  = (const float*)d_in[1];
    const float* b_qkv  = (const float*)d_in[2];
    const float* w_proj = (const float*)d_in[3];
    const float* b_proj = (const float*)d_in[4];
    float* out = (float*)d_out;

    {
        dim3 grid((3 * CC) / 128, (BB * NN) / 128);  // 18 x 64
        qkv_gemm<<<grid, 256>>>(x, w_qkv, b_qkv);
    }
    {
        int smem = (QT * FPH + 64 * FPH + 64 * FPH) * sizeof(__half);  // 55296 B
        cudaFuncSetAttribute(flash_attn, cudaFuncAttributeMaxDynamicSharedMemorySize, smem);
        dim3 grid(NN / QT, BB * HH);  // 8 x 48
        flash_attn<<<grid, 256, smem>>>();
    }
    {
        dim3 grid(CC / 128, (BB * NN) / 128);  // 6 x 64
        proj_gemm<<<grid, 256>>>(w_proj, b_proj, out);
    }
}

// round 7
// speedup vs baseline: 8.5853x; 1.2434x over previous
#include <cuda_runtime.h>
#include <cuda_fp16.h>
#include <math.h>
#include <stdint.h>

// Problem constants
#define BB 4
#define NN 2048
#define CC 768
#define HH 12
#define HDIM 64
#define SCALE 0.125f       // 64^-0.5
#define QSCL 0.18033688f   // SCALE * log2(e)

// Scratch (no cudaMalloc allowed -> __device__ globals)
__device__ __half g_hx[BB * NN * CC];          // x in fp16
__device__ __half g_hwq[CC * 3 * CC];          // w_qkv fp16
__device__ __half g_hwp[CC * CC];              // w_proj fp16
__device__ __half g_q[BB * HH * NN * HDIM];    // pre-scaled by QSCL
__device__ __half g_k[BB * HH * NN * HDIM];
__device__ __half g_v[BB * HH * NN * HDIM];
__device__ __half g_att[BB * NN * CC];         // attention out fp16, [B,N,C]

// ---------------------------------------------------------------------------
// Helpers
// ---------------------------------------------------------------------------

__device__ __forceinline__ uint32_t smem_u32(const void* p) {
    uint32_t a;
    asm("{ .reg .u64 t; cvta.to.shared.u64 t, %1; cvt.u32.u64 %0, t; }" : "=r"(a) : "l"(p));
    return a;
}

__device__ __forceinline__ uint32_t packh2(float lo, float hi) {
    uint32_t r;
    asm("cvt.rn.f16x2.f32 %0, %1, %2;" : "=r"(r) : "f"(hi), "f"(lo));
    return r;
}

__device__ __forceinline__ float ex2f(float x) {
    float y;
    asm("ex2.approx.f32 %0, %1;" : "=f"(y) : "f"(x));
    return y;
}

__device__ __forceinline__ void mma_f16(float c[4],
                                        uint32_t a0, uint32_t a1, uint32_t a2, uint32_t a3,
                                        uint32_t b0, uint32_t b1) {
    asm volatile(
        "mma.sync.aligned.m16n8k16.row.col.f32.f16.f16.f32 "
        "{%0,%1,%2,%3}, {%4,%5,%6,%7}, {%8,%9}, {%0,%1,%2,%3};"
        : "+f"(c[0]), "+f"(c[1]), "+f"(c[2]), "+f"(c[3])
        : "r"(a0), "r"(a1), "r"(a2), "r"(a3), "r"(b0), "r"(b1));
}

__device__ __forceinline__ void ldsm_x4(uint32_t& r0, uint32_t& r1, uint32_t& r2, uint32_t& r3,
                                        uint32_t a) {
    asm volatile("ldmatrix.sync.aligned.m8n8.x4.shared.b16 {%0,%1,%2,%3}, [%4];"
                 : "=r"(r0), "=r"(r1), "=r"(r2), "=r"(r3) : "r"(a));
}
__device__ __forceinline__ void ldsm_x2(uint32_t& r0, uint32_t& r1, uint32_t a) {
    asm volatile("ldmatrix.sync.aligned.m8n8.x2.shared.b16 {%0,%1}, [%2];"
                 : "=r"(r0), "=r"(r1) : "r"(a));
}
__device__ __forceinline__ void ldsm_x2t(uint32_t& r0, uint32_t& r1, uint32_t a) {
    asm volatile("ldmatrix.sync.aligned.m8n8.x2.trans.shared.b16 {%0,%1}, [%2];"
                 : "=r"(r0), "=r"(r1) : "r"(a));
}

// ---------------------------------------------------------------------------
// fp32 -> fp16 preconvert (x, w_qkv, w_proj), 8 floats per thread.
// ---------------------------------------------------------------------------

#define NX 786432   // (4*2048*768)/8
#define NQW 221184  // (768*2304)/8
#define NPW 73728   // (768*768)/8

__global__ __launch_bounds__(256) void convert_fp16(
    const float* __restrict__ x, const float* __restrict__ wq,
    const float* __restrict__ wp)
{
    int i = blockIdx.x * 256 + threadIdx.x;
    const float* src;
    __half* dst;
    int off;
    if (i < NX)            { src = x;  dst = g_hx;  off = i; }
    else if (i < NX + NQW) { src = wq; dst = g_hwq; off = i - NX; }
    else                   { src = wp; dst = g_hwp; off = i - NX - NQW; }
    float4 a = ((const float4*)src)[off * 2];
    float4 b = ((const float4*)src)[off * 2 + 1];
    uint4 u;
    u.x = packh2(a.x, a.y); u.y = packh2(a.z, a.w);
    u.z = packh2(b.x, b.y); u.w = packh2(b.z, b.w);
    ((uint4*)dst)[off] = u;
}

// ---------------------------------------------------------------------------
// fp16 MMA GEMM: CTA 128x128, Kstep=64, 8 warps (64x32 each), 2-stage pipeline.
// As [m][k] pitch 72 halfs; Bs [k][n] pitch 136 halfs. fp16 inputs, no cvt.
// ---------------------------------------------------------------------------

#define APITCH 72
#define BPITCH 136
#define STAGEH 17920            // 128*72 + 64*136 halfs
#define GEMM_SMEM (2 * STAGEH * 2)  // 71680 B

template <int LDW, bool IS_QKV>
__device__ __forceinline__ void gemm_body(
    const __half* __restrict__ A,   // [8192, CC]
    const __half* __restrict__ W,   // [CC, LDW]
    const float* __restrict__ bias,
    float* __restrict__ out)
{
    extern __shared__ __half gsm[];

    const int tid = threadIdx.x;
    const int warp = tid >> 5;
    const int lane = tid & 31;
    const int g = lane >> 2;
    const int tg = lane & 3;

    const int m0 = blockIdx.y * 128;
    const int n0 = blockIdx.x * 128;
    const int warp_m = (warp >> 2) * 64;
    const int warp_n = (warp & 3) * 32;

    const int a_row_off = (lane & 7) + 8 * ((lane >> 3) & 1);
    const int a_col_off = 8 * (lane >> 4);
    const int b_row_off = lane & 15;

    const uint32_t sb[2] = { smem_u32(gsm), smem_u32(gsm + STAGEH) };

    // Load coords: f = tid + it*256, it<4
    int am[4], ac[4], bk[4], bc[4];
#pragma unroll
    for (int it = 0; it < 4; it++) {
        int f = tid + it * 256;
        am[it] = f >> 3;  ac[it] = f & 7;    // A: 128 rows x 8 chunks(8h)
        bk[it] = f >> 4;  bc[it] = f & 15;   // B: 64 rows x 16 chunks
    }

    float acc[4][4][4];
#pragma unroll
    for (int mt = 0; mt < 4; mt++)
#pragma unroll
        for (int nt = 0; nt < 4; nt++)
#pragma unroll
            for (int r = 0; r < 4; r++) acc[mt][nt][r] = 0.f;

    uint4 areg[4], breg[4];

    // Prologue: k-step 0 into stage 0
#pragma unroll
    for (int it = 0; it < 4; it++) {
        areg[it] = *(const uint4*)&A[(m0 + am[it]) * CC + ac[it] * 8];
        breg[it] = *(const uint4*)&W[bk[it] * LDW + n0 + bc[it] * 8];
    }
#pragma unroll
    for (int it = 0; it < 4; it++) {
        *(uint4*)&gsm[am[it] * APITCH + ac[it] * 8] = areg[it];
        *(uint4*)&gsm[128 * APITCH + bk[it] * BPITCH + bc[it] * 8] = breg[it];
    }
    __syncthreads();

    const int NSTEP = CC / 64;  // 12
    for (int ks = 0; ks < NSTEP; ks++) {
        const int b = ks & 1;
        const bool more = (ks + 1 < NSTEP);
        if (more) {
            int k0 = (ks + 1) * 64;
#pragma unroll
            for (int it = 0; it < 4; it++) {
                areg[it] = *(const uint4*)&A[(m0 + am[it]) * CC + k0 + ac[it] * 8];
                breg[it] = *(const uint4*)&W[(k0 + bk[it]) * LDW + n0 + bc[it] * 8];
            }
        }

#pragma unroll
        for (int kc = 0; kc < 4; kc++) {
            uint32_t a[4][4], b0[4], b1[4];
#pragma unroll
            for (int mt = 0; mt < 4; mt++)
                ldsm_x4(a[mt][0], a[mt][1], a[mt][2], a[mt][3],
                        sb[b] + ((warp_m + mt * 16 + a_row_off) * APITCH + kc * 16 + a_col_off) * 2);
#pragma unroll
            for (int nt = 0; nt < 4; nt++)
                ldsm_x2t(b0[nt], b1[nt],
                         sb[b] + (128 * APITCH + (kc * 16 + b_row_off) * BPITCH + warp_n + nt * 8) * 2);
#pragma unroll
            for (int mt = 0; mt < 4; mt++)
#pragma unroll
                for (int nt = 0; nt < 4; nt++)
                    mma_f16(acc[mt][nt], a[mt][0], a[mt][1], a[mt][2], a[mt][3],
                            b0[nt], b1[nt]);
        }

        if (more) {
            __half* dst = gsm + (b ^ 1) * STAGEH;
#pragma unroll
            for (int it = 0; it < 4; it++) {
                *(uint4*)&dst[am[it] * APITCH + ac[it] * 8] = areg[it];
                *(uint4*)&dst[128 * APITCH + bk[it] * BPITCH + bc[it] * 8] = breg[it];
            }
        }
        __syncthreads();
    }

    // Epilogue
#pragma unroll
    for (int mt = 0; mt < 4; mt++) {
#pragma unroll
        for (int nt = 0; nt < 4; nt++) {
#pragma unroll
            for (int half = 0; half < 2; half++) {
                int row = m0 + warp_m + mt * 16 + g + half * 8;
                int col = n0 + warp_n + nt * 8 + 2 * tg;
                float v0 = acc[mt][nt][half * 2 + 0] + bias[col];
                float v1 = acc[mt][nt][half * 2 + 1] + bias[col + 1];
                if (IS_QKV) {
                    int b_ = row >> 11;
                    int n = row & (NN - 1);
                    int three = col / CC;
                    int rem = col - three * CC;
                    int h = rem >> 6;
                    int hd = rem & 63;
                    int idx = ((b_ * HH + h) * NN + n) * HDIM + hd;
                    if (three == 0) {
                        *(uint32_t*)&g_q[idx] = packh2(v0 * QSCL, v1 * QSCL);
                    } else if (three == 1) {
                        *(uint32_t*)&g_k[idx] = packh2(v0, v1);
                    } else {
                        *(uint32_t*)&g_v[idx] = packh2(v0, v1);
                    }
                } else {
                    *(float2*)&out[row * CC + col] = make_float2(v0, v1);
                }
            }
        }
    }
}

__global__ __launch_bounds__(256, 2) void qkv_gemm(const float* __restrict__ bias) {
    gemm_body<3 * CC, true>(g_hx, g_hwq, bias, nullptr);
}

__global__ __launch_bounds__(256, 2) void proj_gemm(const float* __restrict__ bias,
                                                    float* __restrict__ out) {
    gemm_body<CC, false>(g_att, g_hwp, bias, out);
}

// ---------------------------------------------------------------------------
// Flash attention, fp16 mma m16n8k16, fp16 global Q/K/V. One CTA = 256 query
// rows (8 warps x 32), KV tiles of 64. Q frags in registers; P C-frag==A-frag.
// exp2 domain (q pre-scaled by SCALE*log2e).
// ---------------------------------------------------------------------------

#define FPH 72
#define QT 256

__global__ __launch_bounds__(256, 1) void flash_attn() {
    extern __shared__ __half fsm[];
    __half* Qs = fsm;                    // [256][72]
    __half* Ks = Qs + QT * FPH;          // [64][72]
    __half* Vs = Ks + 64 * FPH;          // [64][72]

    const int tid = threadIdx.x;
    const int warp = tid >> 5;
    const int lane = tid & 31;
    const int g = lane >> 2;
    const int tg = lane & 3;
    const int qbase = warp * 32;

    const int bh = blockIdx.y;
    const int n0 = blockIdx.x * QT;

    const __half* __restrict__ Qg = g_q + bh * (NN * HDIM);
    const __half* __restrict__ Kg = g_k + bh * (NN * HDIM);
    const __half* __restrict__ Vg = g_v + bh * (NN * HDIM);

    const uint32_t qsb = smem_u32(Qs);
    const uint32_t ksb = smem_u32(Ks);
    const uint32_t vsb = smem_u32(Vs);

    const int a_row_off = (lane & 7) + 8 * ((lane >> 3) & 1);
    const int a_col_off = 8 * (lane >> 4);
    const int k_row_off = lane & 7;
    const int k_col_off = 8 * ((lane >> 3) & 1);
    const int v_row_off = lane & 15;

    // K/V tile: 64 rows x 8 chunks(8h) = 512 chunks, 2 per thread
    const int ldrow[2] = { tid >> 3, (tid + 256) >> 3 };
    const int ldc8 = (tid & 7) * 8;

    // Load Q tile [256][64] fp16
    {
        const uint4* Qg4 = (const uint4*)(Qg + n0 * HDIM);
#pragma unroll
        for (int it = 0; it < 8; it++) {
            int f = tid + it * 256;
            int row = f >> 3, c8 = (f & 7) * 8;
            *(uint4*)&Qs[row * FPH + c8] = Qg4[f];
        }
    }
    __syncthreads();

    // Hoist Q fragments: qa[mt][kc][4]
    uint32_t qa[2][4][4];
#pragma unroll
    for (int mt = 0; mt < 2; mt++)
#pragma unroll
        for (int kc = 0; kc < 4; kc++)
            ldsm_x4(qa[mt][kc][0], qa[mt][kc][1], qa[mt][kc][2], qa[mt][kc][3],
                    qsb + ((qbase + mt * 16 + a_row_off) * FPH + kc * 16 + a_col_off) * 2);

    float mR[2][2], lR[2][2];
    float o[2][8][4];
#pragma unroll
    for (int mt = 0; mt < 2; mt++) {
        mR[mt][0] = -1e30f; mR[mt][1] = -1e30f;
        lR[mt][0] = 0.f; lR[mt][1] = 0.f;
#pragma unroll
        for (int nt = 0; nt < 8; nt++)
#pragma unroll
            for (int r = 0; r < 4; r++) o[mt][nt][r] = 0.f;
    }

    uint4 kreg[2], vreg[2];
#pragma unroll
    for (int it = 0; it < 2; it++)
        kreg[it] = ((const uint4*)Kg)[tid + it * 256];

    for (int j0 = 0; j0 < NN; j0 += 64) {
        // Store K tile, issue V loads
#pragma unroll
        for (int it = 0; it < 2; it++)
            *(uint4*)&Ks[ldrow[it] * FPH + ldc8] = kreg[it];
#pragma unroll
        for (int it = 0; it < 2; it++)
            vreg[it] = ((const uint4*)(Vg + j0 * HDIM))[tid + it * 256];
        __syncthreads();

        // S = Q @ K^T (in log2 units, q pre-scaled)
        float s[2][8][4];
#pragma unroll
        for (int mt = 0; mt < 2; mt++)
#pragma unroll
            for (int nt = 0; nt < 8; nt++)
#pragma unroll
                for (int r = 0; r < 4; r++) s[mt][nt][r] = 0.f;

#pragma unroll
        for (int kc = 0; kc < 4; kc++) {
#pragma unroll
            for (int nt = 0; nt < 8; nt++) {
                uint32_t b0, b1;
                ldsm_x2(b0, b1,
                        ksb + ((nt * 8 + k_row_off) * FPH + kc * 16 + k_col_off) * 2);
                mma_f16(s[0][nt], qa[0][kc][0], qa[0][kc][1], qa[0][kc][2], qa[0][kc][3], b0, b1);
                mma_f16(s[1][nt], qa[1][kc][0], qa[1][kc][1], qa[1][kc][2], qa[1][kc][3], b0, b1);
            }
        }

        // Online softmax (base-2)
#pragma unroll
        for (int mt = 0; mt < 2; mt++) {
            float tm0 = -1e30f, tm1 = -1e30f;
#pragma unroll
            for (int nt = 0; nt < 8; nt++) {
                tm0 = fmaxf(tm0, fmaxf(s[mt][nt][0], s[mt][nt][1]));
                tm1 = fmaxf(tm1, fmaxf(s[mt][nt][2], s[mt][nt][3]));
            }
            tm0 = fmaxf(tm0, __shfl_xor_sync(0xffffffffu, tm0, 1));
            tm0 = fmaxf(tm0, __shfl_xor_sync(0xffffffffu, tm0, 2));
            tm1 = fmaxf(tm1, __shfl_xor_sync(0xffffffffu, tm1, 1));
            tm1 = fmaxf(tm1, __shfl_xor_sync(0xffffffffu, tm1, 2));

            float nm0 = fmaxf(mR[mt][0], tm0), nm1 = fmaxf(mR[mt][1], tm1);
            float c0 = ex2f(mR[mt][0] - nm0), c1 = ex2f(mR[mt][1] - nm1);
            float sum0 = 0.f, sum1 = 0.f;
#pragma unroll
            for (int nt = 0; nt < 8; nt++) {
                s[mt][nt][0] = ex2f(s[mt][nt][0] - nm0); sum0 += s[mt][nt][0];
                s[mt][nt][1] = ex2f(s[mt][nt][1] - nm0); sum0 += s[mt][nt][1];
                s[mt][nt][2] = ex2f(s[mt][nt][2] - nm1); sum1 += s[mt][nt][2];
                s[mt][nt][3] = ex2f(s[mt][nt][3] - nm1); sum1 += s[mt][nt][3];
            }
            sum0 += __shfl_xor_sync(0xffffffffu, sum0, 1);
            sum0 += __shfl_xor_sync(0xffffffffu, sum0, 2);
            sum1 += __shfl_xor_sync(0xffffffffu, sum1, 1);
            sum1 += __shfl_xor_sync(0xffffffffu, sum1, 2);

            lR[mt][0] = lR[mt][0] * c0 + sum0;
            lR[mt][1] = lR[mt][1] * c1 + sum1;
            mR[mt][0] = nm0; mR[mt][1] = nm1;
#pragma unroll
            for (int nt = 0; nt < 8; nt++) {
                o[mt][nt][0] *= c0; o[mt][nt][1] *= c0;
                o[mt][nt][2] *= c1; o[mt][nt][3] *= c1;
            }
        }

        // Store V tile, prefetch next K
#pragma unroll
        for (int it = 0; it < 2; it++)
            *(uint4*)&Vs[ldrow[it] * FPH + ldc8] = vreg[it];
        if (j0 + 64 < NN) {
#pragma unroll
            for (int it = 0; it < 2; it++)
                kreg[it] = ((const uint4*)(Kg + (j0 + 64) * HDIM))[tid + it * 256];
        }
        __syncthreads();

        // O += P @ V (P A-frags packed straight from S C-frags)
#pragma unroll
        for (int kc = 0; kc < 4; kc++) {
            uint32_t pa[2][4];
#pragma unroll
            for (int mt = 0; mt < 2; mt++) {
                pa[mt][0] = packh2(s[mt][2 * kc][0],     s[mt][2 * kc][1]);
                pa[mt][1] = packh2(s[mt][2 * kc][2],     s[mt][2 * kc][3]);
                pa[mt][2] = packh2(s[mt][2 * kc + 1][0], s[mt][2 * kc + 1][1]);
                pa[mt][3] = packh2(s[mt][2 * kc + 1][2], s[mt][2 * kc + 1][3]);
            }
#pragma unroll
            for (int nt = 0; nt < 8; nt++) {
                uint32_t b0, b1;
                ldsm_x2t(b0, b1, vsb + ((kc * 16 + v_row_off) * FPH + nt * 8) * 2);
                mma_f16(o[0][nt], pa[0][0], pa[0][1], pa[0][2], pa[0][3], b0, b1);
                mma_f16(o[1][nt], pa[1][0], pa[1][1], pa[1][2], pa[1][3], b0, b1);
            }
        }
    }

    // Write O / l to g_att (fp16) in [B, N, C]
    const int b_ = bh / HH;
    const int h = bh % HH;
#pragma unroll
    for (int mt = 0; mt < 2; mt++) {
        float inv0 = 1.f / lR[mt][0], inv1 = 1.f / lR[mt][1];
        int row0 = n0 + qbase + mt * 16 + g;
        int row1 = row0 + 8;
#pragma unroll
        for (int nt = 0; nt < 8; nt++) {
            int col = h * HDIM + nt * 8 + 2 * tg;
            *(uint32_t*)&g_att[(b_ * NN + row0) * CC + col] =
                packh2(o[mt][nt][0] * inv0, o[mt][nt][1] * inv0);
            *(uint32_t*)&g_att[(b_ * NN + row1) * CC + col] =
                packh2(o[mt][nt][2] * inv1, o[mt][nt][3] * inv1);
        }
    }
}

// ---------------------------------------------------------------------------

extern "C" void kernel_launch(void* const* d_in, const int* in_sizes, int n_in,
                              void* d_out, int out_size) {
    const float* x      = (const float*)d_in[0];
    const float* w_qkv  = (const float*)d_in[1];
    const float* b_qkv  = (const float*)d_in[2];
    const float* w_proj = (const float*)d_in[3];
    const float* b_proj = (const float*)d_in[4];
    float* out = (float*)d_out;

    convert_fp16<<<(NX + NQW + NPW) / 256, 256>>>(x, w_qkv, w_proj);

    {
        cudaFuncSetAttribute(qkv_gemm, cudaFuncAttributeMaxDynamicSharedMemorySize, GEMM_SMEM);
        dim3 grid((3 * CC) / 128, (BB * NN) / 128);  // 18 x 64
        qkv_gemm<<<grid, 256, GEMM_SMEM>>>(b_qkv);
    }
    {
        int smem = (QT * FPH + 64 * FPH + 64 * FPH) * sizeof(__half);  // 55296 B
        cudaFuncSetAttribute(flash_attn, cudaFuncAttributeMaxDynamicSharedMemorySize, smem);
        dim3 grid(NN / QT, BB * HH);  // 8 x 48
        flash_attn<<<grid, 256, smem>>>();
    }
    {
        cudaFuncSetAttribute(proj_gemm, cudaFuncAttributeMaxDynamicSharedMemorySize, GEMM_SMEM);
        dim3 grid(CC / 128, (BB * NN) / 128);  // 6 x 64
        proj_gemm<<<grid, 256, GEMM_SMEM>>>(b_proj, out);
    }
}